// round 1
// baseline (speedup 1.0000x reference)
#include <cuda_runtime.h>
#include <cstdint>

// ---------------------------------------------------------------------------
// Decoder: emb gather + concat -> LSTM x2 -> FC -> [B, V, T]
// B=64, T=32, E=H=512, V=32000
// ---------------------------------------------------------------------------
#define B_  64
#define T_  32
#define E_  512
#define H_  512
#define V_  32000
#define M_  (B_ * T_)    // 2048 rows
#define G4_ (4 * H_)     // 2048 gate cols

// Scratch (static device globals: allocation-free rule)
__device__ float g_x0[M_ * E_];      // 4 MB   concat(features, emb shift)
__device__ float g_xp[M_ * G4_];     // 16 MB  input projection (per layer)
__device__ float g_hseq[M_ * H_];    // 4 MB   per-layer h sequence
__device__ float g_hA[B_ * H_];
__device__ float g_hB[B_ * H_];
__device__ float g_c[B_ * H_];

// ---------------------------------------------------------------------------
// helpers
// ---------------------------------------------------------------------------
__device__ __forceinline__ uint32_t f2tf32(float x) {
    uint32_t r;
    asm("cvt.rna.tf32.f32 %0, %1;" : "=r"(r) : "f"(x));
    return r;
}

__device__ __forceinline__ void mma_tf32(float (&c)[4], const uint32_t (&a)[4],
                                         const uint32_t (&b)[2]) {
    asm volatile(
        "mma.sync.aligned.m16n8k8.row.col.f32.tf32.tf32.f32 "
        "{%0,%1,%2,%3}, {%4,%5,%6,%7}, {%8,%9}, {%0,%1,%2,%3};\n"
        : "+f"(c[0]), "+f"(c[1]), "+f"(c[2]), "+f"(c[3])
        : "r"(a[0]), "r"(a[1]), "r"(a[2]), "r"(a[3]), "r"(b[0]), "r"(b[1]));
}

// ---------------------------------------------------------------------------
// x0 build: x[:,0,:]=features ; x[:,t,:]=emb[sentence[:,t-1]] for t>=1
// ---------------------------------------------------------------------------
__global__ void build_x0(const int* __restrict__ sentence,
                         const float* __restrict__ features,
                         const float* __restrict__ emb,
                         float* __restrict__ x0) {
    int i4 = blockIdx.x * blockDim.x + threadIdx.x;  // over M_*E_/4 float4s
    if (i4 >= M_ * (E_ / 4)) return;
    int m  = i4 >> 7;            // row (E_/4 = 128 float4 per row)
    int e4 = (i4 & 127) * 4;
    int b  = m >> 5;
    int t  = m & 31;
    float4 v;
    if (t == 0) {
        v = *(const float4*)&features[b * E_ + e4];
    } else {
        int tok = sentence[b * T_ + (t - 1)];
        v = *(const float4*)&emb[tok * E_ + e4];
    }
    *(float4*)&x0[m * E_ + e4] = v;
}

__global__ void zero_hc(float* __restrict__ h, float* __restrict__ c) {
    int i = blockIdx.x * blockDim.x + threadIdx.x;
    if (i < B_ * H_) { h[i] = 0.f; c[i] = 0.f; }
}

// ---------------------------------------------------------------------------
// tf32 GEMM: C[M,N] = A[M,K] * Bm[N,K]^T + bias1 (+ bias2)
// MODE 0: row-major C.  MODE 1: FC output, write out[b, n, t] with m = b*32+t.
// Block 128x128x32, 256 threads (8 warps: 2m x 4n, warp tile 64x32).
// M, N multiples of 128; K multiple of 32 (exact for all our shapes).
// ---------------------------------------------------------------------------
template <int MODE>
__global__ void __launch_bounds__(256)
gemm_tf32(const float* __restrict__ A, const float* __restrict__ Bm,
          const float* __restrict__ bias1, const float* __restrict__ bias2,
          float* __restrict__ C, int M, int N, int K) {
    const int LDSM = 36;  // pad: (row*36 + k) % 32 = (4*row + k) % 32 -> conflict-free frags
    __shared__ uint32_t As[128 * LDSM];
    __shared__ uint32_t Bs[128 * LDSM];

    int tid  = threadIdx.x;
    int lane = tid & 31;
    int warp = tid >> 5;
    int wm = (warp >> 2) * 64;  // 0 / 64
    int wn = (warp & 3) * 32;   // 0..96
    int m0 = blockIdx.y * 128;
    int n0 = blockIdx.x * 128;

    float acc[4][4][4];
#pragma unroll
    for (int mt = 0; mt < 4; mt++)
#pragma unroll
        for (int nt = 0; nt < 4; nt++)
#pragma unroll
            for (int i = 0; i < 4; i++) acc[mt][nt][i] = 0.f;

    int lrow = tid >> 3;        // 0..31
    int lcol = (tid & 7) * 4;   // 0..28

    for (int k0 = 0; k0 < K; k0 += 32) {
        __syncthreads();
#pragma unroll
        for (int p = 0; p < 4; p++) {
            int row = lrow + p * 32;
            float4 av = *(const float4*)&A[(size_t)(m0 + row) * K + k0 + lcol];
            float4 bv = *(const float4*)&Bm[(size_t)(n0 + row) * K + k0 + lcol];
            As[row * LDSM + lcol + 0] = f2tf32(av.x);
            As[row * LDSM + lcol + 1] = f2tf32(av.y);
            As[row * LDSM + lcol + 2] = f2tf32(av.z);
            As[row * LDSM + lcol + 3] = f2tf32(av.w);
            Bs[row * LDSM + lcol + 0] = f2tf32(bv.x);
            Bs[row * LDSM + lcol + 1] = f2tf32(bv.y);
            Bs[row * LDSM + lcol + 2] = f2tf32(bv.z);
            Bs[row * LDSM + lcol + 3] = f2tf32(bv.w);
        }
        __syncthreads();

#pragma unroll
        for (int ks = 0; ks < 4; ks++) {
            int kb = ks * 8;
            uint32_t af[4][4];
            uint32_t bf[4][2];
#pragma unroll
            for (int mt = 0; mt < 4; mt++) {
                int r = wm + mt * 16 + (lane >> 2);
                int kc = kb + (lane & 3);
                af[mt][0] = As[r * LDSM + kc];
                af[mt][1] = As[(r + 8) * LDSM + kc];
                af[mt][2] = As[r * LDSM + kc + 4];
                af[mt][3] = As[(r + 8) * LDSM + kc + 4];
            }
#pragma unroll
            for (int nt = 0; nt < 4; nt++) {
                int nr = wn + nt * 8 + (lane >> 2);
                int kc = kb + (lane & 3);
                bf[nt][0] = Bs[nr * LDSM + kc];
                bf[nt][1] = Bs[nr * LDSM + kc + 4];
            }
#pragma unroll
            for (int mt = 0; mt < 4; mt++)
#pragma unroll
                for (int nt = 0; nt < 4; nt++) mma_tf32(acc[mt][nt], af[mt], bf[nt]);
        }
    }

    // epilogue
#pragma unroll
    for (int nt = 0; nt < 4; nt++) {
        int cn  = n0 + wn + nt * 8 + (lane & 3) * 2;
        float bv0 = bias1[cn];
        float bv1 = bias1[cn + 1];
        if (bias2) { bv0 += bias2[cn]; bv1 += bias2[cn + 1]; }
#pragma unroll
        for (int mt = 0; mt < 4; mt++) {
            int r = m0 + wm + mt * 16 + (lane >> 2);
            float v0 = acc[mt][nt][0] + bv0;
            float v1 = acc[mt][nt][1] + bv1;
            float v2 = acc[mt][nt][2] + bv0;
            float v3 = acc[mt][nt][3] + bv1;
            if (MODE == 0) {
                C[(size_t)r * N + cn]           = v0;
                C[(size_t)r * N + cn + 1]       = v1;
                C[(size_t)(r + 8) * N + cn]     = v2;
                C[(size_t)(r + 8) * N + cn + 1] = v3;
            } else {
                // out[b, v, t] : m = b*32 + t
                int b1 = r >> 5, t1 = r & 31;
                int b2 = (r + 8) >> 5, t2 = (r + 8) & 31;
                size_t base1 = (size_t)b1 * N * T_ + t1;
                size_t base2 = (size_t)b2 * N * T_ + t2;
                C[base1 + (size_t)cn * T_]       = v0;
                C[base1 + (size_t)(cn + 1) * T_] = v1;
                C[base2 + (size_t)cn * T_]       = v2;
                C[base2 + (size_t)(cn + 1) * T_] = v3;
            }
        }
    }
}

// ---------------------------------------------------------------------------
// LSTM step: gates = xp[:,t,:] + h_in @ Whh^T ; nonlinearity ; update c, h.
// Grid 128 blocks, each owns 4 h-columns for all 64 batches.
// 256 threads: b = tid & 63, jl = tid >> 6.
// h and W chunks staged in smem (K chunked by 128 to fit 48KB static smem).
// h double-buffered across steps (h_in read by ALL blocks).
// ---------------------------------------------------------------------------
__global__ void __launch_bounds__(256)
lstm_step(const float* __restrict__ xp, const float* __restrict__ Whh,
          const float* __restrict__ h_in, float* __restrict__ h_out,
          float* __restrict__ c, float* __restrict__ hseq, int t) {
    __shared__ float hs[B_ * 132];   // [b][kk], stride 132 (4b+kk banks, f4-phase clean)
    __shared__ float ws[16 * 132];   // [g*4+jl][kk]

    int tid = threadIdx.x;
    int b   = tid & 63;
    int jl  = tid >> 6;                 // 0..3
    int j   = blockIdx.x * 4 + jl;      // h column

    float acc[4];
#pragma unroll
    for (int g = 0; g < 4; g++)
        acc[g] = xp[(size_t)(b * T_ + t) * G4_ + g * H_ + j];

    for (int kb = 0; kb < H_; kb += 128) {
        __syncthreads();
        // stage h chunk: 64 x 128 floats = 2048 float4, 8 per thread
#pragma unroll
        for (int i = tid; i < 64 * 32; i += 256) {
            int bb = i >> 5;
            int k4 = (i & 31) * 4;
            float4 v = *(const float4*)&h_in[bb * H_ + kb + k4];
            *(float4*)&hs[bb * 132 + k4] = v;
        }
        // stage W chunk: 16 rows x 128 floats = 512 float4, 2 per thread
#pragma unroll
        for (int i = tid; i < 512; i += 256) {
            int r  = i >> 5;            // 0..15 = gate*4 + jcol
            int k4 = (i & 31) * 4;
            int gg = r >> 2, jj = r & 3;
            float4 v = *(const float4*)&Whh[(size_t)(gg * H_ + blockIdx.x * 4 + jj) * H_ + kb + k4];
            *(float4*)&ws[r * 132 + k4] = v;
        }
        __syncthreads();

#pragma unroll 4
        for (int kk = 0; kk < 128; kk += 4) {
            float4 hv = *(const float4*)&hs[b * 132 + kk];
#pragma unroll
            for (int g = 0; g < 4; g++) {
                float4 wv = *(const float4*)&ws[(g * 4 + jl) * 132 + kk];
                acc[g] += hv.x * wv.x + hv.y * wv.y + hv.z * wv.z + hv.w * wv.w;
            }
        }
    }

    float ig = 1.f / (1.f + __expf(-acc[0]));
    float fg = 1.f / (1.f + __expf(-acc[1]));
    float gg = tanhf(acc[2]);
    float og = 1.f / (1.f + __expf(-acc[3]));

    float cold = c[b * H_ + j];
    float cn   = fg * cold + ig * gg;
    float hn   = og * tanhf(cn);

    c[b * H_ + j]                        = cn;
    h_out[b * H_ + j]                    = hn;
    hseq[(size_t)(b * T_ + t) * H_ + j]  = hn;
}

// ---------------------------------------------------------------------------
// launch
// ---------------------------------------------------------------------------
extern "C" void kernel_launch(void* const* d_in, const int* in_sizes, int n_in,
                              void* d_out, int out_size) {
    (void)in_sizes; (void)n_in; (void)out_size;
    const int*   sentence = (const int*)d_in[0];
    const float* features = (const float*)d_in[1];
    // d_in[2] = lengths (unused by reference output)
    const float* emb   = (const float*)d_in[3];
    const float* W_ih0 = (const float*)d_in[4];
    const float* W_hh0 = (const float*)d_in[5];
    const float* b_ih0 = (const float*)d_in[6];
    const float* b_hh0 = (const float*)d_in[7];
    const float* W_ih1 = (const float*)d_in[8];
    const float* W_hh1 = (const float*)d_in[9];
    const float* b_ih1 = (const float*)d_in[10];
    const float* b_hh1 = (const float*)d_in[11];
    const float* fc_W  = (const float*)d_in[12];
    const float* fc_b  = (const float*)d_in[13];
    float* out = (float*)d_out;

    float *x0, *xp, *hseq, *hA, *hB, *cb;
    cudaGetSymbolAddress((void**)&x0, g_x0);
    cudaGetSymbolAddress((void**)&xp, g_xp);
    cudaGetSymbolAddress((void**)&hseq, g_hseq);
    cudaGetSymbolAddress((void**)&hA, g_hA);
    cudaGetSymbolAddress((void**)&hB, g_hB);
    cudaGetSymbolAddress((void**)&cb, g_c);

    // 1) build x0
    build_x0<<<(M_ * (E_ / 4) + 255) / 256, 256>>>(sentence, features, emb, x0);

    // 2) layer 0 input projection: xp = x0 @ W_ih0^T + b_ih0 + b_hh0
    gemm_tf32<0><<<dim3(G4_ / 128, M_ / 128), 256>>>(x0, W_ih0, b_ih0, b_hh0, xp,
                                                     M_, G4_, E_);
    // 3) layer 0 recurrence
    zero_hc<<<(B_ * H_ + 255) / 256, 256>>>(hA, cb);
    for (int t = 0; t < T_; t++) {
        const float* hin = (t & 1) ? hB : hA;
        float*       hout = (t & 1) ? hA : hB;
        lstm_step<<<H_ / 4, 256>>>(xp, W_hh0, hin, hout, cb, hseq, t);
    }

    // 4) layer 1 input projection: xp = hseq @ W_ih1^T + b_ih1 + b_hh1
    gemm_tf32<0><<<dim3(G4_ / 128, M_ / 128), 256>>>(hseq, W_ih1, b_ih1, b_hh1, xp,
                                                     M_, G4_, H_);
    // 5) layer 1 recurrence (overwrites hseq — safe: projection already consumed it)
    zero_hc<<<(B_ * H_ + 255) / 256, 256>>>(hA, cb);
    for (int t = 0; t < T_; t++) {
        const float* hin = (t & 1) ? hB : hA;
        float*       hout = (t & 1) ? hA : hB;
        lstm_step<<<H_ / 4, 256>>>(xp, W_hh1, hin, hout, cb, hseq, t);
    }

    // 6) FC + transpose: out[b, v, t] = hseq[b*T+t] . fc_W[v] + fc_b[v]
    gemm_tf32<1><<<dim3(V_ / 128, M_ / 128), 256>>>(hseq, fc_W, fc_b, nullptr, out,
                                                    M_, V_, H_);
}

// round 2
// speedup vs baseline: 1.2280x; 1.2280x over previous
#include <cuda_runtime.h>
#include <cstdint>

// ---------------------------------------------------------------------------
// Decoder: emb gather + concat -> LSTM x2 (persistent, tensor-core) -> FC
// B=64, T=32, E=H=512, V=32000
// ---------------------------------------------------------------------------
#define B_  64
#define T_  32
#define E_  512
#define H_  512
#define V_  32000
#define M_  (B_ * T_)    // 2048
#define G4_ (4 * H_)     // 2048
#define NB_ 64           // persistent blocks (all co-resident on 148 SMs)

__device__ float g_x0[M_ * E_];
__device__ float g_xp[M_ * G4_];
__device__ float g_hseq[M_ * H_];
__device__ float g_h0[B_ * H_];
__device__ float g_h1[B_ * H_];
__device__ unsigned g_cnt;
__device__ unsigned g_sense;

// ---------------------------------------------------------------------------
__device__ __forceinline__ uint32_t f2tf32(float x) {
    uint32_t r;
    asm("cvt.rna.tf32.f32 %0, %1;" : "=r"(r) : "f"(x));
    return r;
}

__device__ __forceinline__ void mma_tf32(float (&c)[4], const uint32_t (&a)[4],
                                         const uint32_t (&b)[2]) {
    asm volatile(
        "mma.sync.aligned.m16n8k8.row.col.f32.tf32.tf32.f32 "
        "{%0,%1,%2,%3}, {%4,%5,%6,%7}, {%8,%9}, {%0,%1,%2,%3};\n"
        : "+f"(c[0]), "+f"(c[1]), "+f"(c[2]), "+f"(c[3])
        : "r"(a[0]), "r"(a[1]), "r"(a[2]), "r"(a[3]), "r"(b[0]), "r"(b[1]));
}

// ---------------------------------------------------------------------------
__global__ void build_x0(const int* __restrict__ sentence,
                         const float* __restrict__ features,
                         const float* __restrict__ emb,
                         float* __restrict__ x0) {
    int i4 = blockIdx.x * blockDim.x + threadIdx.x;
    if (i4 >= M_ * (E_ / 4)) return;
    int m  = i4 >> 7;
    int e4 = (i4 & 127) * 4;
    int b  = m >> 5;
    int t  = m & 31;
    float4 v;
    if (t == 0) {
        v = *(const float4*)&features[b * E_ + e4];
    } else {
        int tok = sentence[b * T_ + (t - 1)];
        v = *(const float4*)&emb[tok * E_ + e4];
    }
    *(float4*)&x0[m * E_ + e4] = v;
}

__global__ void reset_bar() { g_cnt = 0; g_sense = 0; }

// ---------------------------------------------------------------------------
// tf32 GEMM with register prefetch. C = A[M,K] * Bm[N,K]^T + bias1 (+bias2)
// MODE 0: row-major C.  MODE 1: out[b, n, t], m = b*32 + t.
// ---------------------------------------------------------------------------
template <int MODE>
__global__ void __launch_bounds__(256)
gemm_tf32(const float* __restrict__ A, const float* __restrict__ Bm,
          const float* __restrict__ bias1, const float* __restrict__ bias2,
          float* __restrict__ C, int M, int N, int K) {
    const int LDSM = 36;
    __shared__ uint32_t As[128 * LDSM];
    __shared__ uint32_t Bs[128 * LDSM];

    int tid  = threadIdx.x;
    int lane = tid & 31;
    int warp = tid >> 5;
    int wm = (warp >> 2) * 64;
    int wn = (warp & 3) * 32;
    int m0 = blockIdx.y * 128;
    int n0 = blockIdx.x * 128;

    float acc[4][4][4];
#pragma unroll
    for (int mt = 0; mt < 4; mt++)
#pragma unroll
        for (int nt = 0; nt < 4; nt++)
#pragma unroll
            for (int i = 0; i < 4; i++) acc[mt][nt][i] = 0.f;

    int lrow = tid >> 3;
    int lcol = (tid & 7) * 4;

    float4 pa[4], pb[4];
#pragma unroll
    for (int p = 0; p < 4; p++) {
        pa[p] = *(const float4*)&A[(size_t)(m0 + lrow + p * 32) * K + lcol];
        pb[p] = *(const float4*)&Bm[(size_t)(n0 + lrow + p * 32) * K + lcol];
    }

    for (int k0 = 0; k0 < K; k0 += 32) {
        __syncthreads();
#pragma unroll
        for (int p = 0; p < 4; p++) {
            int row = lrow + p * 32;
            As[row * LDSM + lcol + 0] = f2tf32(pa[p].x);
            As[row * LDSM + lcol + 1] = f2tf32(pa[p].y);
            As[row * LDSM + lcol + 2] = f2tf32(pa[p].z);
            As[row * LDSM + lcol + 3] = f2tf32(pa[p].w);
            Bs[row * LDSM + lcol + 0] = f2tf32(pb[p].x);
            Bs[row * LDSM + lcol + 1] = f2tf32(pb[p].y);
            Bs[row * LDSM + lcol + 2] = f2tf32(pb[p].z);
            Bs[row * LDSM + lcol + 3] = f2tf32(pb[p].w);
        }
        __syncthreads();
        if (k0 + 32 < K) {
#pragma unroll
            for (int p = 0; p < 4; p++) {
                pa[p] = *(const float4*)&A[(size_t)(m0 + lrow + p * 32) * K + k0 + 32 + lcol];
                pb[p] = *(const float4*)&Bm[(size_t)(n0 + lrow + p * 32) * K + k0 + 32 + lcol];
            }
        }

#pragma unroll
        for (int ks = 0; ks < 4; ks++) {
            int kb = ks * 8;
            uint32_t af[4][4];
            uint32_t bf[4][2];
#pragma unroll
            for (int mt = 0; mt < 4; mt++) {
                int r = wm + mt * 16 + (lane >> 2);
                int kc = kb + (lane & 3);
                af[mt][0] = As[r * LDSM + kc];
                af[mt][1] = As[(r + 8) * LDSM + kc];
                af[mt][2] = As[r * LDSM + kc + 4];
                af[mt][3] = As[(r + 8) * LDSM + kc + 4];
            }
#pragma unroll
            for (int nt = 0; nt < 4; nt++) {
                int nr = wn + nt * 8 + (lane >> 2);
                int kc = kb + (lane & 3);
                bf[nt][0] = Bs[nr * LDSM + kc];
                bf[nt][1] = Bs[nr * LDSM + kc + 4];
            }
#pragma unroll
            for (int mt = 0; mt < 4; mt++)
#pragma unroll
                for (int nt = 0; nt < 4; nt++) mma_tf32(acc[mt][nt], af[mt], bf[nt]);
        }
    }

#pragma unroll
    for (int nt = 0; nt < 4; nt++) {
        int cn  = n0 + wn + nt * 8 + (lane & 3) * 2;
        float bv0 = bias1[cn];
        float bv1 = bias1[cn + 1];
        if (bias2) { bv0 += bias2[cn]; bv1 += bias2[cn + 1]; }
#pragma unroll
        for (int mt = 0; mt < 4; mt++) {
            int r = m0 + wm + mt * 16 + (lane >> 2);
            float v0 = acc[mt][nt][0] + bv0;
            float v1 = acc[mt][nt][1] + bv1;
            float v2 = acc[mt][nt][2] + bv0;
            float v3 = acc[mt][nt][3] + bv1;
            if (MODE == 0) {
                C[(size_t)r * N + cn]           = v0;
                C[(size_t)r * N + cn + 1]       = v1;
                C[(size_t)(r + 8) * N + cn]     = v2;
                C[(size_t)(r + 8) * N + cn + 1] = v3;
            } else {
                int b1 = r >> 5, t1 = r & 31;
                int b2 = (r + 8) >> 5, t2 = (r + 8) & 31;
                size_t base1 = (size_t)b1 * N * T_ + t1;
                size_t base2 = (size_t)b2 * N * T_ + t2;
                C[base1 + (size_t)cn * T_]       = v0;
                C[base1 + (size_t)(cn + 1) * T_] = v1;
                C[base2 + (size_t)cn * T_]       = v2;
                C[base2 + (size_t)(cn + 1) * T_] = v3;
            }
        }
    }
}

// ---------------------------------------------------------------------------
// Persistent LSTM layer. 64 blocks x 256 threads; block owns 32 gate cols
// (4 gates x 8 h-cols, j0 = blockIdx*8). Whh fragments live in registers for
// all 32 steps. Per step: stage h into fragment-shuffled tf32 smem, K-split
// mma across 8 warps, smem reduce, fused gate epilogue (c in registers),
// double-buffered global h, software grid barrier.
// smem: hsf 32768 floats (128KB) + red 16384 floats (64KB) = 192KB dynamic.
// ---------------------------------------------------------------------------
__global__ void __launch_bounds__(256, 1)
lstm_layer(const float* __restrict__ xp, const float* __restrict__ Whh,
           float* __restrict__ hb0, float* __restrict__ hb1,
           float* __restrict__ hseq) {
    extern __shared__ float sm[];
    float* hsf = sm;           // [mt(4)][kt(64)][ai(4)][32]
    float* red = sm + 32768;   // [w(8)][mt(4)][nt(4)][128]

    const int tid  = threadIdx.x;
    const int lane = tid & 31;
    const int w    = tid >> 5;
    const int gid  = lane >> 2;
    const int tig  = lane & 3;
    const int j0   = blockIdx.x * 8;

    // Whh fragments -> registers (once). n = nt*8+gid -> W row nt*512+j0+gid.
    uint32_t bfr[4][8][2];
#pragma unroll
    for (int nt = 0; nt < 4; nt++)
#pragma unroll
        for (int ktl = 0; ktl < 8; ktl++) {
            int k   = w * 64 + ktl * 8 + tig;
            int row = nt * H_ + j0 + gid;
            bfr[nt][ktl][0] = f2tf32(Whh[(size_t)row * H_ + k]);
            bfr[nt][ktl][1] = f2tf32(Whh[(size_t)row * H_ + k + 4]);
        }

    // zero hsf (t=0 h is zero)
#pragma unroll 4
    for (int i = tid; i < 8192; i += 256)
        *(float4*)&hsf[i * 4] = make_float4(0.f, 0.f, 0.f, 0.f);

    const int jj = tid & 7;
    const int bq = tid >> 3;   // 0..31 ; handles batches bq and bq+32
    float creg0 = 0.f, creg1 = 0.f;

    for (int t = 0; t < T_; t++) {
        if (t > 0) {
            // stage h (written last step) -> fragment-shuffled tf32 smem
            const float* hsrc = ((t & 1) == 0) ? hb1 : hb0;  // buf[(t-1)&1]
#pragma unroll
            for (int it = 0; it < 32; it++) {
                int idx = it * 256 + tid;
                int b = idx >> 7, q = idx & 127;
                float4 v = __ldcg((const float4*)(hsrc + b * H_ + q * 4));
                int mt = b >> 4, r = b & 15;
                int kt = q >> 1;
                int ai = (r >> 3) | ((q & 1) << 1);
                uint32_t* dst =
                    (uint32_t*)&hsf[(((mt * 64 + kt) * 4 + ai) << 5) + (r & 7) * 4];
                dst[0] = f2tf32(v.x); dst[1] = f2tf32(v.y);
                dst[2] = f2tf32(v.z); dst[3] = f2tf32(v.w);
            }
        }
        __syncthreads();

        // K-split mma: warp w owns k in [64w, 64w+64)
        float acc[4][4][4];
#pragma unroll
        for (int mt = 0; mt < 4; mt++)
#pragma unroll
            for (int nt = 0; nt < 4; nt++)
#pragma unroll
                for (int i = 0; i < 4; i++) acc[mt][nt][i] = 0.f;

#pragma unroll
        for (int ktl = 0; ktl < 8; ktl++) {
            int ktg = w * 8 + ktl;
            uint32_t a[4][4];
#pragma unroll
            for (int mt = 0; mt < 4; mt++) {
                const uint32_t* s =
                    (const uint32_t*)&hsf[((mt * 64 + ktg) << 7) + lane];
                a[mt][0] = s[0];  a[mt][1] = s[32];
                a[mt][2] = s[64]; a[mt][3] = s[96];
            }
#pragma unroll
            for (int mt = 0; mt < 4; mt++)
#pragma unroll
                for (int nt = 0; nt < 4; nt++)
                    mma_tf32(acc[mt][nt], a[mt], bfr[nt][ktl]);
        }

        // store K-partials
#pragma unroll
        for (int mt = 0; mt < 4; mt++)
#pragma unroll
            for (int nt = 0; nt < 4; nt++) {
                float* dst = &red[(((w * 4 + mt) * 4 + nt) << 7) + lane * 4];
                dst[0] = acc[mt][nt][0]; dst[1] = acc[mt][nt][1];
                dst[2] = acc[mt][nt][2]; dst[3] = acc[mt][nt][3];
            }
        __syncthreads();

        // epilogue: 2 outputs per thread
        float* hdst = (t & 1) ? hb1 : hb0;
#pragma unroll
        for (int half = 0; half < 2; half++) {
            int b     = bq + half * 32;
            int row_t = b & 15;
            int mt    = b >> 4;
            int pos   = (((row_t & 7) * 4 + (jj >> 1)) << 2) + (jj & 1) +
                        ((row_t >> 3) << 1);
            float gv[4];
#pragma unroll
            for (int g = 0; g < 4; g++) {
                float s = xp[(size_t)(b * T_ + t) * G4_ + g * H_ + j0 + jj];
#pragma unroll
                for (int ww = 0; ww < 8; ww++)
                    s += red[(((ww * 4 + mt) * 4 + g) << 7) + pos];
                gv[g] = s;
            }
            float ig = 1.f / (1.f + __expf(-gv[0]));
            float fg = 1.f / (1.f + __expf(-gv[1]));
            float gg = tanhf(gv[2]);
            float og = 1.f / (1.f + __expf(-gv[3]));
            float cold = half ? creg1 : creg0;
            float cn = fg * cold + ig * gg;
            if (half) creg1 = cn; else creg0 = cn;
            float hn = og * tanhf(cn);
            hdst[b * H_ + j0 + jj]                     = hn;
            hseq[(size_t)(b * T_ + t) * H_ + j0 + jj]  = hn;
        }

        // grid barrier (64 blocks, all co-resident)
        __threadfence();
        __syncthreads();
        if (tid == 0) {
            unsigned target = (unsigned)(t + 1);
            if (atomicAdd(&g_cnt, 1) == NB_ - 1) {
                g_cnt = 0;
                __threadfence();
                atomicExch(&g_sense, target);
            } else {
                while (*(volatile unsigned*)&g_sense < target) { }
            }
            __threadfence();
        }
        __syncthreads();
    }
}

// ---------------------------------------------------------------------------
extern "C" void kernel_launch(void* const* d_in, const int* in_sizes, int n_in,
                              void* d_out, int out_size) {
    (void)in_sizes; (void)n_in; (void)out_size;
    const int*   sentence = (const int*)d_in[0];
    const float* features = (const float*)d_in[1];
    const float* emb   = (const float*)d_in[3];
    const float* W_ih0 = (const float*)d_in[4];
    const float* W_hh0 = (const float*)d_in[5];
    const float* b_ih0 = (const float*)d_in[6];
    const float* b_hh0 = (const float*)d_in[7];
    const float* W_ih1 = (const float*)d_in[8];
    const float* W_hh1 = (const float*)d_in[9];
    const float* b_ih1 = (const float*)d_in[10];
    const float* b_hh1 = (const float*)d_in[11];
    const float* fc_W  = (const float*)d_in[12];
    const float* fc_b  = (const float*)d_in[13];
    float* out = (float*)d_out;

    float *x0, *xp, *hseq, *h0, *h1;
    cudaGetSymbolAddress((void**)&x0, g_x0);
    cudaGetSymbolAddress((void**)&xp, g_xp);
    cudaGetSymbolAddress((void**)&hseq, g_hseq);
    cudaGetSymbolAddress((void**)&h0, g_h0);
    cudaGetSymbolAddress((void**)&h1, g_h1);

    static bool attr_set = false;
    if (!attr_set) {
        cudaFuncSetAttribute(lstm_layer,
                             cudaFuncAttributeMaxDynamicSharedMemorySize,
                             196608);
        attr_set = true;
    }

    build_x0<<<(M_ * (E_ / 4) + 255) / 256, 256>>>(sentence, features, emb, x0);

    gemm_tf32<0><<<dim3(G4_ / 128, M_ / 128), 256>>>(x0, W_ih0, b_ih0, b_hh0,
                                                     xp, M_, G4_, E_);
    reset_bar<<<1, 1>>>();
    lstm_layer<<<NB_, 256, 196608>>>(xp, W_hh0, h0, h1, hseq);

    gemm_tf32<0><<<dim3(G4_ / 128, M_ / 128), 256>>>(hseq, W_ih1, b_ih1, b_hh1,
                                                     xp, M_, G4_, H_);
    reset_bar<<<1, 1>>>();
    lstm_layer<<<NB_, 256, 196608>>>(xp, W_hh1, h0, h1, hseq);

    gemm_tf32<1><<<dim3(V_ / 128, M_ / 128), 256>>>(hseq, fc_W, fc_b, nullptr,
                                                    out, M_, V_, H_);
}

// round 3
// speedup vs baseline: 1.5907x; 1.2953x over previous
#include <cuda_runtime.h>
#include <cstdint>

// ---------------------------------------------------------------------------
// Decoder: emb gather + concat -> LSTM x2 (persistent, tensor-core) -> FC
// B=64, T=32, E=H=512, V=32000
// ---------------------------------------------------------------------------
#define B_  64
#define T_  32
#define E_  512
#define H_  512
#define V_  32000
#define M_  (B_ * T_)    // 2048
#define G4_ (4 * H_)     // 2048
#define NB_ 64           // persistent blocks

__device__ float    g_x0[M_ * E_];
__device__ float    g_xp[M_ * G4_];
__device__ float    g_hseq[M_ * H_];
__device__ uint32_t g_hf0[B_ * H_];   // h in fragment-shuffled tf32 layout
__device__ uint32_t g_hf1[B_ * H_];
__device__ unsigned g_cnt;
__device__ unsigned g_sense;

// ---------------------------------------------------------------------------
__device__ __forceinline__ uint32_t f2tf32(float x) {
    uint32_t r;
    asm("cvt.rna.tf32.f32 %0, %1;" : "=r"(r) : "f"(x));
    return r;
}

__device__ __forceinline__ void mma_tf32(float (&c)[4], const uint32_t (&a)[4],
                                         const uint32_t (&b)[2]) {
    asm volatile(
        "mma.sync.aligned.m16n8k8.row.col.f32.tf32.tf32.f32 "
        "{%0,%1,%2,%3}, {%4,%5,%6,%7}, {%8,%9}, {%0,%1,%2,%3};\n"
        : "+f"(c[0]), "+f"(c[1]), "+f"(c[2]), "+f"(c[3])
        : "r"(a[0]), "r"(a[1]), "r"(a[2]), "r"(a[3]), "r"(b[0]), "r"(b[1]));
}

__device__ __forceinline__ unsigned atom_add_rel(unsigned* p) {
    unsigned old;
    asm volatile("atom.release.gpu.global.add.u32 %0, [%1], 1;"
                 : "=r"(old) : "l"(p) : "memory");
    return old;
}
__device__ __forceinline__ void st_rel(unsigned* p, unsigned v) {
    asm volatile("st.release.gpu.global.u32 [%0], %1;" :: "l"(p), "r"(v)
                 : "memory");
}
__device__ __forceinline__ unsigned ld_acq(unsigned* p) {
    unsigned v;
    asm volatile("ld.acquire.gpu.global.u32 %0, [%1];" : "=r"(v) : "l"(p)
                 : "memory");
    return v;
}

// ---------------------------------------------------------------------------
__global__ void build_x0(const int* __restrict__ sentence,
                         const float* __restrict__ features,
                         const float* __restrict__ emb,
                         float* __restrict__ x0) {
    int i4 = blockIdx.x * blockDim.x + threadIdx.x;
    if (i4 >= M_ * (E_ / 4)) return;
    int m  = i4 >> 7;
    int e4 = (i4 & 127) * 4;
    int b  = m >> 5;
    int t  = m & 31;
    float4 v;
    if (t == 0) {
        v = *(const float4*)&features[b * E_ + e4];
    } else {
        int tok = sentence[b * T_ + (t - 1)];
        v = *(const float4*)&emb[tok * E_ + e4];
    }
    *(float4*)&x0[m * E_ + e4] = v;
}

__global__ void reset_bar() { g_cnt = 0; g_sense = 0; }

// ---------------------------------------------------------------------------
// tf32 GEMM (register prefetch). C = A[M,K] * Bm[N,K]^T + bias1 (+bias2)
// MODE 0: row-major C.  MODE 1: out[b, n, t], m = b*32 + t.
// ---------------------------------------------------------------------------
template <int MODE>
__global__ void __launch_bounds__(256)
gemm_tf32(const float* __restrict__ A, const float* __restrict__ Bm,
          const float* __restrict__ bias1, const float* __restrict__ bias2,
          float* __restrict__ C, int M, int N, int K) {
    const int LDSM = 36;
    __shared__ uint32_t As[128 * LDSM];
    __shared__ uint32_t Bs[128 * LDSM];

    int tid  = threadIdx.x;
    int lane = tid & 31;
    int warp = tid >> 5;
    int wm = (warp >> 2) * 64;
    int wn = (warp & 3) * 32;
    int m0 = blockIdx.y * 128;
    int n0 = blockIdx.x * 128;

    float acc[4][4][4];
#pragma unroll
    for (int mt = 0; mt < 4; mt++)
#pragma unroll
        for (int nt = 0; nt < 4; nt++)
#pragma unroll
            for (int i = 0; i < 4; i++) acc[mt][nt][i] = 0.f;

    int lrow = tid >> 3;
    int lcol = (tid & 7) * 4;

    float4 pa[4], pb[4];
#pragma unroll
    for (int p = 0; p < 4; p++) {
        pa[p] = *(const float4*)&A[(size_t)(m0 + lrow + p * 32) * K + lcol];
        pb[p] = *(const float4*)&Bm[(size_t)(n0 + lrow + p * 32) * K + lcol];
    }

    for (int k0 = 0; k0 < K; k0 += 32) {
        __syncthreads();
#pragma unroll
        for (int p = 0; p < 4; p++) {
            int row = lrow + p * 32;
            As[row * LDSM + lcol + 0] = f2tf32(pa[p].x);
            As[row * LDSM + lcol + 1] = f2tf32(pa[p].y);
            As[row * LDSM + lcol + 2] = f2tf32(pa[p].z);
            As[row * LDSM + lcol + 3] = f2tf32(pa[p].w);
            Bs[row * LDSM + lcol + 0] = f2tf32(pb[p].x);
            Bs[row * LDSM + lcol + 1] = f2tf32(pb[p].y);
            Bs[row * LDSM + lcol + 2] = f2tf32(pb[p].z);
            Bs[row * LDSM + lcol + 3] = f2tf32(pb[p].w);
        }
        __syncthreads();
        if (k0 + 32 < K) {
#pragma unroll
            for (int p = 0; p < 4; p++) {
                pa[p] = *(const float4*)&A[(size_t)(m0 + lrow + p * 32) * K + k0 + 32 + lcol];
                pb[p] = *(const float4*)&Bm[(size_t)(n0 + lrow + p * 32) * K + k0 + 32 + lcol];
            }
        }

#pragma unroll
        for (int ks = 0; ks < 4; ks++) {
            int kb = ks * 8;
            uint32_t af[4][4];
            uint32_t bf[4][2];
#pragma unroll
            for (int mt = 0; mt < 4; mt++) {
                int r = wm + mt * 16 + (lane >> 2);
                int kc = kb + (lane & 3);
                af[mt][0] = As[r * LDSM + kc];
                af[mt][1] = As[(r + 8) * LDSM + kc];
                af[mt][2] = As[r * LDSM + kc + 4];
                af[mt][3] = As[(r + 8) * LDSM + kc + 4];
            }
#pragma unroll
            for (int nt = 0; nt < 4; nt++) {
                int nr = wn + nt * 8 + (lane >> 2);
                int kc = kb + (lane & 3);
                bf[nt][0] = Bs[nr * LDSM + kc];
                bf[nt][1] = Bs[nr * LDSM + kc + 4];
            }
#pragma unroll
            for (int mt = 0; mt < 4; mt++)
#pragma unroll
                for (int nt = 0; nt < 4; nt++) mma_tf32(acc[mt][nt], af[mt], bf[nt]);
        }
    }

#pragma unroll
    for (int nt = 0; nt < 4; nt++) {
        int cn  = n0 + wn + nt * 8 + (lane & 3) * 2;
        float bv0 = bias1[cn];
        float bv1 = bias1[cn + 1];
        if (bias2) { bv0 += bias2[cn]; bv1 += bias2[cn + 1]; }
#pragma unroll
        for (int mt = 0; mt < 4; mt++) {
            int r = m0 + wm + mt * 16 + (lane >> 2);
            float v0 = acc[mt][nt][0] + bv0;
            float v1 = acc[mt][nt][1] + bv1;
            float v2 = acc[mt][nt][2] + bv0;
            float v3 = acc[mt][nt][3] + bv1;
            if (MODE == 0) {
                C[(size_t)r * N + cn]           = v0;
                C[(size_t)r * N + cn + 1]       = v1;
                C[(size_t)(r + 8) * N + cn]     = v2;
                C[(size_t)(r + 8) * N + cn + 1] = v3;
            } else {
                int b1 = r >> 5, t1 = r & 31;
                int b2 = (r + 8) >> 5, t2 = (r + 8) & 31;
                size_t base1 = (size_t)b1 * N * T_ + t1;
                size_t base2 = (size_t)b2 * N * T_ + t2;
                C[base1 + (size_t)cn * T_]       = v0;
                C[base1 + (size_t)(cn + 1) * T_] = v1;
                C[base2 + (size_t)cn * T_]       = v2;
                C[base2 + (size_t)(cn + 1) * T_] = v3;
            }
        }
    }
}

// ---------------------------------------------------------------------------
// Persistent LSTM layer. 64 blocks x 256 threads; block owns 32 gate cols
// (4 gates x 8 h-cols, j0 = blockIdx*8). Whh fragments in registers for all
// 32 steps. h double buffers live in GLOBAL memory already in the mma
// fragment-shuffled tf32 layout (producer-side shuffle), so staging is a
// flat 128KB ldcg->sts.128 copy and A-fragment loads are single LDS.128.
// hsf layout: u32[mt(4)][kt(64)][lane(32)][ai(4)]
// ---------------------------------------------------------------------------
__global__ void __launch_bounds__(256, 1)
lstm_layer(const float* __restrict__ xp, const float* __restrict__ Whh,
           uint32_t* __restrict__ hf0, uint32_t* __restrict__ hf1,
           float* __restrict__ hseq) {
    extern __shared__ uint32_t smu[];
    uint32_t* hsf = smu;            // 32768 u32 = 128KB
    float*    red = (float*)(smu + 32768);  // 16384 f = 64KB: [w8][mt4][nt4][128]

    const int tid  = threadIdx.x;
    const int lane = tid & 31;
    const int w    = tid >> 5;
    const int gid  = lane >> 2;
    const int tig  = lane & 3;
    const int j0   = blockIdx.x * 8;
    const int kt_o = blockIdx.x;     // j0 >> 3

    // Whh fragments -> registers (once)
    uint32_t bfr[4][8][2];
#pragma unroll
    for (int nt = 0; nt < 4; nt++)
#pragma unroll
        for (int ktl = 0; ktl < 8; ktl++) {
            int k   = w * 64 + ktl * 8 + tig;
            int row = nt * H_ + j0 + gid;
            bfr[nt][ktl][0] = f2tf32(Whh[(size_t)row * H_ + k]);
            bfr[nt][ktl][1] = f2tf32(Whh[(size_t)row * H_ + k + 4]);
        }

    // zero hsf (t=0 h is zero)
#pragma unroll 4
    for (int i = tid; i < 8192; i += 256)
        *(uint4*)&hsf[i * 4] = make_uint4(0u, 0u, 0u, 0u);

    const int jj = tid & 7;
    const int bq = tid >> 3;   // handles batches bq and bq+32
    float creg0 = 0.f, creg1 = 0.f;

    for (int t = 0; t < T_; t++) {
        // prefetch xp[t] (independent of h) — overlaps barrier wait + staging
        float xpr[2][4];
#pragma unroll
        for (int half = 0; half < 2; half++) {
            int b = bq + half * 32;
#pragma unroll
            for (int g = 0; g < 4; g++)
                xpr[half][g] = xp[(size_t)(b * T_ + t) * G4_ + g * H_ + j0 + jj];
        }

        if (t > 0) {
            // wait for all blocks to have finished step t-1
            if (tid == 0) {
                while (ld_acq(&g_sense) < (unsigned)t) { }
            }
            __syncthreads();
            // stage h[t-1] (already fragment-shuffled tf32): flat 128KB copy
            const uint4* src = (const uint4*)((t & 1) ? hf0 : hf1);
#pragma unroll
            for (int it = 0; it < 32; it++) {
                int idx = it * 256 + tid;
                uint4 v = __ldcg(src + idx);
                *(uint4*)&hsf[idx * 4] = v;
            }
        }
        __syncthreads();

        // K-split mma: warp w owns k in [64w, 64w+64)
        float acc[4][4][4];
#pragma unroll
        for (int mt = 0; mt < 4; mt++)
#pragma unroll
            for (int nt = 0; nt < 4; nt++)
#pragma unroll
                for (int i = 0; i < 4; i++) acc[mt][nt][i] = 0.f;

#pragma unroll
        for (int ktl = 0; ktl < 8; ktl++) {
            int ktg = w * 8 + ktl;
            uint32_t a[4][4];
#pragma unroll
            for (int mt = 0; mt < 4; mt++) {
                uint4 av = *(const uint4*)&hsf[(((mt * 64 + ktg) * 32) + lane) * 4];
                a[mt][0] = av.x; a[mt][1] = av.y; a[mt][2] = av.z; a[mt][3] = av.w;
            }
#pragma unroll
            for (int mt = 0; mt < 4; mt++)
#pragma unroll
                for (int nt = 0; nt < 4; nt++)
                    mma_tf32(acc[mt][nt], a[mt], bfr[nt][ktl]);
        }

        // store K-partials (vectorized)
#pragma unroll
        for (int mt = 0; mt < 4; mt++)
#pragma unroll
            for (int nt = 0; nt < 4; nt++)
                *(float4*)&red[(((w * 4 + mt) * 4 + nt) << 7) + lane * 4] =
                    make_float4(acc[mt][nt][0], acc[mt][nt][1],
                                acc[mt][nt][2], acc[mt][nt][3]);
        __syncthreads();

        // epilogue: 2 outputs per thread
        uint32_t* hdst = (t & 1) ? hf1 : hf0;
        const int e   = jj & 3;
        const int qlo = jj >> 2;
#pragma unroll
        for (int half = 0; half < 2; half++) {
            int b     = bq + half * 32;
            int row_t = b & 15;
            int mt    = b >> 4;
            int pos   = (((row_t & 7) * 4 + (jj >> 1)) << 2) + (jj & 1) +
                        ((row_t >> 3) << 1);
            float gv[4];
#pragma unroll
            for (int g = 0; g < 4; g++) {
                float s = xpr[half][g];
#pragma unroll
                for (int ww = 0; ww < 8; ww++)
                    s += red[(((ww * 4 + mt) * 4 + g) << 7) + pos];
                gv[g] = s;
            }
            float ig = 1.f / (1.f + __expf(-gv[0]));
            float fg = 1.f / (1.f + __expf(-gv[1]));
            float gg = tanhf(gv[2]);
            float og = 1.f / (1.f + __expf(-gv[3]));
            float cold = half ? creg1 : creg0;
            float cn = fg * cold + ig * gg;
            if (half) creg1 = cn; else creg0 = cn;
            float hn = og * tanhf(cn);
            // fragment-shuffled tf32 store for next step's A operand
            int lane_p = (b & 7) * 4 + e;
            int ai     = ((b >> 3) & 1) | (qlo << 1);
            hdst[((mt * 64 + kt_o) * 32 + lane_p) * 4 + ai] = f2tf32(hn);
            // row-major for downstream GEMMs
            hseq[(size_t)(b * T_ + t) * H_ + j0 + jj] = hn;
        }

        if (t < T_ - 1) {
            __syncthreads();
            if (tid == 0) {
                unsigned old = atom_add_rel(&g_cnt);
                if (old == (unsigned)(NB_ * (t + 1) - 1))
                    st_rel(&g_sense, (unsigned)(t + 1));
            }
        }
    }
}

// ---------------------------------------------------------------------------
extern "C" void kernel_launch(void* const* d_in, const int* in_sizes, int n_in,
                              void* d_out, int out_size) {
    (void)in_sizes; (void)n_in; (void)out_size;
    const int*   sentence = (const int*)d_in[0];
    const float* features = (const float*)d_in[1];
    const float* emb   = (const float*)d_in[3];
    const float* W_ih0 = (const float*)d_in[4];
    const float* W_hh0 = (const float*)d_in[5];
    const float* b_ih0 = (const float*)d_in[6];
    const float* b_hh0 = (const float*)d_in[7];
    const float* W_ih1 = (const float*)d_in[8];
    const float* W_hh1 = (const float*)d_in[9];
    const float* b_ih1 = (const float*)d_in[10];
    const float* b_hh1 = (const float*)d_in[11];
    const float* fc_W  = (const float*)d_in[12];
    const float* fc_b  = (const float*)d_in[13];
    float* out = (float*)d_out;

    float *x0, *xp, *hseq;
    uint32_t *hf0, *hf1;
    cudaGetSymbolAddress((void**)&x0, g_x0);
    cudaGetSymbolAddress((void**)&xp, g_xp);
    cudaGetSymbolAddress((void**)&hseq, g_hseq);
    cudaGetSymbolAddress((void**)&hf0, g_hf0);
    cudaGetSymbolAddress((void**)&hf1, g_hf1);

    cudaFuncSetAttribute(lstm_layer,
                         cudaFuncAttributeMaxDynamicSharedMemorySize, 196608);

    build_x0<<<(M_ * (E_ / 4) + 255) / 256, 256>>>(sentence, features, emb, x0);

    gemm_tf32<0><<<dim3(G4_ / 128, M_ / 128), 256>>>(x0, W_ih0, b_ih0, b_hh0,
                                                     xp, M_, G4_, E_);
    reset_bar<<<1, 1>>>();
    lstm_layer<<<NB_, 256, 196608>>>(xp, W_hh0, hf0, hf1, hseq);

    gemm_tf32<0><<<dim3(G4_ / 128, M_ / 128), 256>>>(hseq, W_ih1, b_ih1, b_hh1,
                                                     xp, M_, G4_, H_);
    reset_bar<<<1, 1>>>();
    lstm_layer<<<NB_, 256, 196608>>>(xp, W_hh1, hf0, hf1, hseq);

    gemm_tf32<1><<<dim3(V_ / 128, M_ / 128), 256>>>(hseq, fc_W, fc_b, nullptr,
                                                    out, M_, V_, H_);
}